// round 4
// baseline (speedup 1.0000x reference)
#include <cuda_runtime.h>
#include <cuda_bf16.h>

#define BSZ 8
#define CH  64
#define H   256
#define W   256
#define HW  (H*W)
#define EPS 1e-5f
#define SLOPE 0.01f
#define CROP 244

typedef unsigned long long u64;

#define FMA2(d,a,b,c) asm("fma.rn.f32x2 %0, %1, %2, %3;" : "=l"(d) : "l"(a), "l"(b), "l"(c))
#define PACK2(d,lo,hi) asm("mov.b64 %0, {%1, %2};" : "=l"(d) : "f"(lo), "f"(hi))
#define UNPK2(lo,hi,d) asm("mov.b64 {%0, %1}, %2;" : "=f"(lo), "=f"(hi) : "l"(d))

// ---------------- scratch (no allocs allowed) ----------------
__device__ float g_actA[BSZ*CH*HW];
__device__ float g_actB[BSZ*CH*HW];
__device__ float g_stats[8*BSZ*CH*2];
__device__ float g_norm[8*BSZ*CH*2];
__device__ float g_loss_sb[169*BSZ];

__global__ void zero_stats_kernel() {
    for (int i = threadIdx.x; i < 8*BSZ*CH*2; i += blockDim.x)
        g_stats[i] = 0.f;
}

// ---- rolling 2-row dup window: only rows kh, kh+1 live during tap step kh ----
// dup layout: 6 packed {v,v} operands built from 6 row floats
#define LOAD_DUP_ROW(dst, bufptr, r)                                        \
    {                                                                       \
        const float* _row = (bufptr) + ((ph*2 + (r))*36 + pw*4);            \
        float4 _v4 = *reinterpret_cast<const float4*>(_row);                \
        float2 _v2 = *reinterpret_cast<const float2*>(_row + 4);            \
        PACK2((dst)[0], _v4.x, _v4.x);                                      \
        PACK2((dst)[1], _v4.y, _v4.y);                                      \
        PACK2((dst)[2], _v4.z, _v4.z);                                      \
        PACK2((dst)[3], _v4.w, _v4.w);                                      \
        PACK2((dst)[4], _v2.x, _v2.x);                                      \
        PACK2((dst)[5], _v2.y, _v2.y);                                      \
    }

// ---------------- fused conv: f32x2, rolling rows, 3 CTAs/SM ----------------
// block tile: 16 co x 16 h x 32 w, 256 threads, thread = 4co x 2h x 4w
__global__ __launch_bounds__(256, 3)
void conv_kernel(const float* __restrict__ in,
                 const float* __restrict__ wgt,    // [16*gridDim.y][cin][9]
                 const float* __restrict__ bias,
                 const float* __restrict__ innorm, // [BSZ*cin*2] or nullptr
                 float* __restrict__ out,
                 float* __restrict__ statacc,
                 int cin)
{
    __shared__ float s_w[64*9*16];     // [ci][tap][co_l]  36864 B
    __shared__ float s_in[2][18*36];   // dbl buffered, padded stride 36

    const int tid   = threadIdx.x;
    const int tileW = blockIdx.x & 7;
    const int tileH = blockIdx.x >> 3;
    const int co_base = blockIdx.y * 16;
    const int b = blockIdx.z;

    const int nw = cin * 9 * 16;
    for (int g = tid; g < nw; g += 256) {
        int co_l = g & 15;
        int ct   = g >> 4;
        int ci   = ct / 9;
        int t    = ct - ci*9;
        s_w[g] = wgt[((co_base + co_l)*cin + ci)*9 + t];
    }

    const int sp = tid & 63, cg = tid >> 6;
    const int ph = sp >> 3, pw = sp & 7;
    const int h0 = tileH*16 + ph*2;
    const int w0 = tileW*32 + pw*4;
    const int hbase = tileH*16 - 1, wbase = tileW*32 - 1;

    int srcO[3], dstO[3]; bool act[3];
    #pragma unroll
    for (int k = 0; k < 3; k++) {
        int g = tid + k*256;
        act[k] = (g < 612);               // 18*34 valid
        int gg = act[k] ? g : 0;
        int r = gg / 34, c = gg - r*34;
        int gh = hbase + r; gh = gh < 0 ? 0 : (gh > H-1 ? H-1 : gh);
        int gw = wbase + c; gw = gw < 0 ? 0 : (gw > W-1 ? W-1 : gw);
        srcO[k] = gh*W + gw;
        dstO[k] = r*36 + c;
    }

    const float* inb = in + (size_t)b * cin * HW;
    const float2* nrmb = innorm ? (const float2*)(innorm + (size_t)b*cin*2) : nullptr;

    // prologue: tile 0 -> buf 0 (IN+LReLU folded into fill)
    {
        float mean = 0.f, rstd = 1.f;
        if (nrmb) { float2 mr = nrmb[0]; mean = mr.x; rstd = mr.y; }
        #pragma unroll
        for (int k = 0; k < 3; k++) if (act[k]) {
            float v = inb[srcO[k]];
            if (nrmb) { v = (v - mean) * rstd; v = v >= 0.f ? v : SLOPE * v; }
            s_in[0][dstO[k]] = v;
        }
    }
    __syncthreads();   // also covers s_w

    u64 acc[2][2][4];
    #pragma unroll
    for (int p = 0; p < 2; p++)
        #pragma unroll
        for (int i = 0; i < 2; i++)
            #pragma unroll
            for (int j = 0; j < 4; j++) acc[p][i][j] = 0ull;

    for (int ci = 0; ci < cin; ci++) {
        const int buf = ci & 1;
        const int cn = (ci + 1 < cin) ? ci + 1 : cin - 1;

        // prefetch next channel tile (3 LDG) + norm params
        float pre[3];
        float2 nmr = nrmb ? nrmb[cn] : make_float2(0.f, 1.f);
        {
            const float* pn = inb + (size_t)cn * HW;
            #pragma unroll
            for (int k = 0; k < 3; k++) pre[k] = act[k] ? pn[srcO[k]] : 0.f;
        }

        const float* bufp = s_in[buf];
        const float* wrow = &s_w[ci*9*16 + cg*4];

        // rolling window: dup[kh&1] = row kh (i=0), dup[(kh+1)&1] = row kh+1 (i=1)
        u64 dup[2][6];
        LOAD_DUP_ROW(dup[0], bufp, 0);
        LOAD_DUP_ROW(dup[1], bufp, 1);

        #pragma unroll
        for (int kh = 0; kh < 3; kh++) {
            const int lo = kh & 1, hi = (kh + 1) & 1;
            u64 wv0[3], wv1[3];
            #pragma unroll
            for (int t = 0; t < 3; t++) {
                wv0[t] = *reinterpret_cast<const u64*>(&wrow[(kh*3 + t)*16    ]);
                wv1[t] = *reinterpret_cast<const u64*>(&wrow[(kh*3 + t)*16 + 2]);
            }
            #pragma unroll
            for (int kw = 0; kw < 3; kw++)
                #pragma unroll
                for (int j = 0; j < 4; j++) {
                    FMA2(acc[0][0][j], dup[lo][j+kw], wv0[kw], acc[0][0][j]);
                    FMA2(acc[0][1][j], dup[hi][j+kw], wv0[kw], acc[0][1][j]);
                    FMA2(acc[1][0][j], dup[lo][j+kw], wv1[kw], acc[1][0][j]);
                    FMA2(acc[1][1][j], dup[hi][j+kw], wv1[kw], acc[1][1][j]);
                }
            if (kh < 2) LOAD_DUP_ROW(dup[lo], bufp, kh + 2);
        }

        // commit prefetched tile to the other buffer
        #pragma unroll
        for (int k = 0; k < 3; k++) if (act[k]) {
            float v = pre[k];
            if (nrmb) { v = (v - nmr.x) * nmr.y; v = v >= 0.f ? v : SLOPE * v; }
            s_in[buf ^ 1][dstO[k]] = v;
        }
        __syncthreads();
    }

    // epilogue: unpack, bias, store, per-(b,co) stats
    #pragma unroll
    for (int p = 0; p < 2; p++) {
        const int co0 = co_base + cg*4 + 2*p;
        const float bv0 = bias[co0], bv1 = bias[co0 + 1];
        float* ob0 = out + (size_t)(b*CH + co0    ) * HW;
        float* ob1 = out + (size_t)(b*CH + co0 + 1) * HW;
        float s0 = 0.f, q0 = 0.f, s1 = 0.f, q1 = 0.f;
        #pragma unroll
        for (int i = 0; i < 2; i++) {
            float lo[4], hi[4];
            #pragma unroll
            for (int j = 0; j < 4; j++) {
                float l, h;
                UNPK2(l, h, acc[p][i][j]);
                lo[j] = l + bv0; hi[j] = h + bv1;
                s0 += lo[j]; q0 += lo[j]*lo[j];
                s1 += hi[j]; q1 += hi[j]*hi[j];
            }
            *reinterpret_cast<float4*>(&ob0[(h0+i)*W + w0]) = make_float4(lo[0],lo[1],lo[2],lo[3]);
            *reinterpret_cast<float4*>(&ob1[(h0+i)*W + w0]) = make_float4(hi[0],hi[1],hi[2],hi[3]);
        }
        #pragma unroll
        for (int off = 16; off; off >>= 1) {
            s0 += __shfl_down_sync(0xffffffffu, s0, off);
            q0 += __shfl_down_sync(0xffffffffu, q0, off);
            s1 += __shfl_down_sync(0xffffffffu, s1, off);
            q1 += __shfl_down_sync(0xffffffffu, q1, off);
        }
        if ((tid & 31) == 0) {
            atomicAdd(&statacc[(b*CH + co0)*2    ], s0);
            atomicAdd(&statacc[(b*CH + co0)*2 + 1], q0);
            atomicAdd(&statacc[(b*CH + co0+1)*2    ], s1);
            atomicAdd(&statacc[(b*CH + co0+1)*2 + 1], q1);
        }
    }
}

// ---------------- stats -> (mean, rstd) ----------------
__global__ void finalize_kernel(const float* __restrict__ acc, float* __restrict__ nrm) {
    int i = blockIdx.x * blockDim.x + threadIdx.x;
    if (i < BSZ*CH) {
        const float inv = 1.f / (float)HW;
        float m = acc[2*i] * inv;
        float v = acc[2*i + 1] * inv - m*m;
        nrm[2*i]     = m;
        nrm[2*i + 1] = rsqrtf(v + EPS);
    }
}

// ---------------- projection conv (64->1) + residual ----------------
__global__ __launch_bounds__(256)
void proj_kernel(const float* __restrict__ in, const float* __restrict__ innorm,
                 const float* __restrict__ wgt, const float* __restrict__ bias,
                 const float* __restrict__ xIn, float* __restrict__ out)
{
    __shared__ float s_w[64*9];
    __shared__ float s_in[18*18];
    const int tid = threadIdx.x;
    const int tileH = blockIdx.x >> 4, tileW = blockIdx.x & 15;
    const int b = blockIdx.z;

    for (int g = tid; g < 576; g += 256) s_w[g] = wgt[g];

    const int ph = tid >> 4, pw = tid & 15;
    const int h = tileH*16 + ph, w = tileW*16 + pw;
    const int hbase = tileH*16 - 1, wbase = tileW*16 - 1;
    const float* inb = in + (size_t)b * CH * HW;

    float acc = 0.f;
    for (int ci = 0; ci < CH; ci++) {
        __syncthreads();
        float mean = innorm[(b*CH + ci)*2];
        float rstd = innorm[(b*CH + ci)*2 + 1];
        const float* p = inb + ci * HW;
        for (int g = tid; g < 18*18; g += 256) {
            int r = g / 18, c = g - r*18;
            int gh = hbase + r; gh = gh < 0 ? 0 : (gh > H-1 ? H-1 : gh);
            int gw = wbase + c; gw = gw < 0 ? 0 : (gw > W-1 ? W-1 : gw);
            float v = p[gh*W + gw];
            v = (v - mean) * rstd;
            v = v >= 0.f ? v : SLOPE * v;
            s_in[g] = v;
        }
        __syncthreads();
        const float* wv = &s_w[ci*9];
        #pragma unroll
        for (int kh = 0; kh < 3; kh++)
            #pragma unroll
            for (int kw = 0; kw < 3; kw++)
                acc = fmaf(s_in[(ph + kh)*18 + pw + kw], wv[kh*3 + kw], acc);
    }
    int idx = b*HW + h*W + w;
    out[idx] = acc + bias[0] + xIn[idx];
}

// ---------------- shift-search loss ----------------
__global__ __launch_bounds__(256)
void loss_kernel(const float* __restrict__ hr, const float* __restrict__ tgt,
                 float* __restrict__ loss_sb)
{
    const int s = blockIdx.x, b = blockIdx.y;
    const int sy = s / 13, sx = s - sy*13;
    const float* hp = hr + (size_t)b * HW;
    const float* tp = tgt + (size_t)b * HW;
    const int tid = threadIdx.x;

    float sum = 0.f, sq = 0.f;
    if (tid < CROP) {
        for (int r = 0; r < CROP; r++) {
            float d = hp[(sy + r)*W + sx + tid] - tp[(6 + r)*W + 6 + tid];
            sum += d; sq += d*d;
        }
    }
    __shared__ float s1[256], s2[256];
    s1[tid] = sum; s2[tid] = sq;
    __syncthreads();
    for (int off = 128; off; off >>= 1) {
        if (tid < off) { s1[tid] += s1[tid + off]; s2[tid] += s2[tid + off]; }
        __syncthreads();
    }
    if (tid == 0) {
        const float invN = 1.f / (float)(CROP*CROP);
        float m = s1[0] * invN;
        loss_sb[s*BSZ + b] = s2[0] * invN - m*m;
    }
}

__global__ void loss_final_kernel(const float* __restrict__ loss_sb, float* __restrict__ out) {
    __shared__ float mn[BSZ];
    int t = threadIdx.x;
    if (t < BSZ) {
        float m = loss_sb[t];
        for (int s = 1; s < 169; s++) m = fminf(m, loss_sb[s*BSZ + t]);
        mn[t] = m;
    }
    __syncthreads();
    if (t == 0) {
        float a = 0.f;
        for (int b = 0; b < BSZ; b++) a += mn[b];
        out[0] = a * (1.f / BSZ);
    }
}

// ---------------- launch ----------------
extern "C" void kernel_launch(void* const* d_in, const int* in_sizes, int n_in,
                              void* d_out, int out_size)
{
    const float* xIn    = (const float*)d_in[0];
    const float* target = (const float*)d_in[1];
    const float* w0     = (const float*)d_in[2];
    const float* b0     = (const float*)d_in[3];
    const float* ws     = (const float*)d_in[4];
    const float* bs     = (const float*)d_in[5];
    const float* wp     = (const float*)d_in[6];
    const float* bp     = (const float*)d_in[7];
    float* out = (float*)d_out;

    float *actA, *actB, *stats, *nrm, *lsb;
    cudaGetSymbolAddress((void**)&actA,  g_actA);
    cudaGetSymbolAddress((void**)&actB,  g_actB);
    cudaGetSymbolAddress((void**)&stats, g_stats);
    cudaGetSymbolAddress((void**)&nrm,   g_norm);
    cudaGetSymbolAddress((void**)&lsb,   g_loss_sb);

    zero_stats_kernel<<<1, 256>>>();

    dim3 cgrid(128, 4, BSZ);

    conv_kernel<<<cgrid, 256>>>(xIn, w0, b0, nullptr, actA, stats, 1);
    finalize_kernel<<<2, 256>>>(stats, nrm);

    const float* cur = actA;
    float* nxt = actB;
    for (int i = 0; i < 7; i++) {
        conv_kernel<<<cgrid, 256>>>(cur, ws + (size_t)i*64*64*9, bs + i*64,
                                    nrm + (size_t)i*BSZ*CH*2, nxt,
                                    stats + (size_t)(i+1)*BSZ*CH*2, 64);
        finalize_kernel<<<2, 256>>>(stats + (size_t)(i+1)*BSZ*CH*2,
                                    nrm   + (size_t)(i+1)*BSZ*CH*2);
        float* tmp = (float*)cur; cur = nxt; nxt = tmp;
    }

    proj_kernel<<<dim3(256, 1, BSZ), 256>>>(cur, nrm + (size_t)7*BSZ*CH*2,
                                            wp, bp, xIn, out);
    loss_kernel<<<dim3(169, BSZ), 256>>>(out, target, lsb);
    loss_final_kernel<<<1, 32>>>(lsb, out + (out_size - 1));
}

// round 7
// speedup vs baseline: 3.5815x; 3.5815x over previous
#include <cuda_runtime.h>
#include <cuda_bf16.h>
#include <cstdint>

#define BSZ 8
#define CH  64
#define H   256
#define W   256
#define HW  (H*W)
#define EPS 1e-5f
#define SLOPE 0.01f
#define CROP 244

typedef unsigned long long u64;

#define FMA2(d,a,b,c) asm("fma.rn.f32x2 %0, %1, %2, %3;" : "=l"(d) : "l"(a), "l"(b), "l"(c))
#define PACK2(d,lo,hi) asm("mov.b64 %0, {%1, %2};" : "=l"(d) : "f"(lo), "f"(hi))
#define UNPK2(lo,hi,d) asm("mov.b64 {%0, %1}, %2;" : "=f"(lo), "=f"(hi) : "l"(d))

__device__ __forceinline__ uint32_t smem_u32(const void* p) {
    uint32_t a;
    asm("{ .reg .u64 t; cvta.to.shared.u64 t, %1; cvt.u32.u64 %0, t; }" : "=r"(a) : "l"(p));
    return a;
}
__device__ __forceinline__ void ldsm4(uint32_t* r, uint32_t addr) {
    asm volatile("ldmatrix.sync.aligned.m8n8.x4.shared.b16 {%0,%1,%2,%3}, [%4];"
                 : "=r"(r[0]), "=r"(r[1]), "=r"(r[2]), "=r"(r[3]) : "r"(addr));
}
__device__ __forceinline__ void mma16816(float* d, const uint32_t* a, const uint32_t* b) {
    asm volatile("mma.sync.aligned.m16n8k16.row.col.f32.bf16.bf16.f32 "
                 "{%0,%1,%2,%3}, {%4,%5,%6,%7}, {%8,%9}, {%0,%1,%2,%3};"
                 : "+f"(d[0]), "+f"(d[1]), "+f"(d[2]), "+f"(d[3])
                 : "r"(a[0]), "r"(a[1]), "r"(a[2]), "r"(a[3]), "r"(b[0]), "r"(b[1]));
}

// ---------------- scratch ----------------
__device__ float g_actA[BSZ*CH*HW];
__device__ float g_actB[BSZ*CH*HW];
__device__ float g_stats[8*BSZ*CH*2];
__device__ float g_norm[8*BSZ*CH*2];
__device__ float g_loss_sb[169*BSZ];
__device__ __nv_bfloat16 g_wprep[7*9*2*4096];   // [layer][tap][hi/lo][64co x 64ci swizzled]

__global__ void zero_stats_kernel() {
    for (int i = threadIdx.x; i < 8*BSZ*CH*2; i += blockDim.x) g_stats[i] = 0.f;
}

// ---------------- weight prep: bf16 split + ldmatrix swizzle image ----------------
// layout: byte_off = co*128 + (((ci>>3) ^ (co&7))<<4) + (ci&7)*2
__global__ void wprep_kernel(const float* __restrict__ ws) {
    const int t = blockIdx.x;    // tap 0..8
    const int l = blockIdx.y;    // layer 0..6
    char* dst_hi = (char*)(g_wprep + (size_t)((l*9 + t)*2    )*4096);
    char* dst_lo = (char*)(g_wprep + (size_t)((l*9 + t)*2 + 1)*4096);
    for (int g = threadIdx.x; g < 4096; g += blockDim.x) {
        int co = g >> 6, ci = g & 63;
        float w = ws[(((size_t)l*64 + co)*64 + ci)*9 + t];
        __nv_bfloat16 hi = __float2bfloat16(w);
        __nv_bfloat16 lo = __float2bfloat16(w - __bfloat162float(hi));
        uint32_t off = (uint32_t)co*128 + ((((uint32_t)ci >> 3) ^ (co & 7)) << 4) + (ci & 7)*2;
        *(__nv_bfloat16*)(dst_hi + off) = hi;
        *(__nv_bfloat16*)(dst_lo + off) = lo;
    }
}

// ---------------- HMMA conv layer ----------------
// smem: window hi [204*128B], window lo [204*128B], B hi [8KB], B lo [8KB], nrm [512B]
#define OF_WHI 0
#define OF_WLO 26112
#define OF_B   52224
#define OF_NRM 68608
#define SMEM_MMA 69120

__global__ void __launch_bounds__(256, 2)
mma_conv_kernel(const float* __restrict__ in,
                const __nv_bfloat16* __restrict__ wp,   // this layer: [9][2][4096]
                const float* __restrict__ bias,
                const float* __restrict__ nrm,          // [BSZ*64*2] (mean,rstd)
                float* __restrict__ out,
                float* __restrict__ statacc)            // [BSZ*64*2]
{
    extern __shared__ char smem[];
    const uint32_t sb = smem_u32(smem);
    const int tid = threadIdx.x;
    const int wid = tid >> 5, lane = tid & 31;
    const int tileW = blockIdx.x;   // 0..7
    const int tileH = blockIdx.y;   // 0..63
    const int b = blockIdx.z;

    // preload norm params for the 64 input channels
    if (tid < 64)
        *(float2*)(smem + OF_NRM + tid*8) = ((const float2*)nrm)[b*64 + tid];
    __syncthreads();   // nrm visible to ALL warps before window fill reads it

    // ---- window fill: 204 pixels (6h x 34w) x 64 ci, IN+LReLU+split, swizzled ----
    if (tid < 204) {
        const int r = tid / 34, c = tid - r*34;
        int gh = tileH*4 - 1 + r; gh = gh < 0 ? 0 : (gh > H-1 ? H-1 : gh);
        int gw = tileW*32 - 1 + c; gw = gw < 0 ? 0 : (gw > W-1 ? W-1 : gw);
        const float* src = in + (size_t)b*64*HW + gh*W + gw;
        const uint32_t rowoff = (uint32_t)tid * 128;
        const int rsw = tid & 7;
        #pragma unroll 1
        for (int chunk = 0; chunk < 8; chunk++) {
            unsigned short hb[8], lb[8];
            #pragma unroll
            for (int q = 0; q < 8; q++) {
                int ci = chunk*8 + q;
                float2 mr = *(const float2*)(smem + OF_NRM + ci*8);
                float x = __ldg(src + (size_t)ci*HW);
                x = (x - mr.x) * mr.y;
                x = x >= 0.f ? x : SLOPE * x;
                __nv_bfloat16 h = __float2bfloat16(x);
                __nv_bfloat16 l = __float2bfloat16(x - __bfloat162float(h));
                hb[q] = *(unsigned short*)&h;
                lb[q] = *(unsigned short*)&l;
            }
            const uint32_t u = (uint32_t)((chunk ^ rsw) << 4);
            *(uint4*)(smem + OF_WHI + rowoff + u) = *(uint4*)hb;
            *(uint4*)(smem + OF_WLO + rowoff + u) = *(uint4*)lb;
        }
    }

    // ---- stage B for tap 0 ----
    const uint4* wp4 = (const uint4*)wp;   // [9][1024] uint4 (hi 512 then lo 512)
    #pragma unroll
    for (int it = 0; it < 4; it++) {
        int g = tid + it*256;
        *(uint4*)(smem + OF_B + (uint32_t)g*16) = __ldg(wp4 + g);
    }
    __syncthreads();

    // warp geometry
    const int hl  = wid >> 1;            // 0..3
    const int wlb = (wid & 1) * 16;      // 0 or 16
    const int gA  = lane >> 3;           // ldmatrix group
    const int rl  = (lane & 7) + (gA & 1)*8;
    const int aK  = gA >> 1;
    const int bRow = (lane & 7) + ((lane >> 4) & 1)*8;
    const int bK   = (lane >> 3) & 1;
    const int bsw  = lane & 7;

    float d[8][4];
    #pragma unroll
    for (int n = 0; n < 8; n++)
        #pragma unroll
        for (int j = 0; j < 4; j++) d[n][j] = 0.f;

    #pragma unroll 1
    for (int t = 0; t < 9; t++) {
        // prefetch next tap's B image
        uint4 pre[4];
        if (t < 8) {
            const uint4* np = wp4 + (size_t)(t + 1)*1024;
            #pragma unroll
            for (int it = 0; it < 4; it++) pre[it] = __ldg(np + tid + it*256);
        }

        const int kh = t / 3, kw = t - kh*3;
        const int wrA = (hl + kh)*34 + wlb + kw + rl;
        const uint32_t aHi = sb + OF_WHI + (uint32_t)wrA*128;
        const uint32_t aLo = sb + OF_WLO + (uint32_t)wrA*128;
        const int asw = wrA & 7;
        const uint32_t bHiB = sb + OF_B;
        const uint32_t bLoB = sb + OF_B + 8192;

        #pragma unroll
        for (int ks = 0; ks < 4; ks++) {
            uint32_t ah[4], al[4];
            const uint32_t ca = (uint32_t)(((2*ks + aK) ^ asw) << 4);
            ldsm4(ah, aHi + ca);
            ldsm4(al, aLo + ca);
            const uint32_t cb = (uint32_t)(2*ks + bK);
            const uint32_t cboff = ((cb ^ (uint32_t)bsw) << 4);
            #pragma unroll
            for (int nbq = 0; nbq < 4; nbq++) {
                const uint32_t boff = (uint32_t)(nbq*16 + bRow)*128 + cboff;
                uint32_t bh[4], bl[4];
                ldsm4(bh, bHiB + boff);
                ldsm4(bl, bLoB + boff);
                mma16816(d[2*nbq    ], ah, bh    );
                mma16816(d[2*nbq    ], al, bh    );
                mma16816(d[2*nbq    ], ah, bl    );
                mma16816(d[2*nbq + 1], ah, bh + 2);
                mma16816(d[2*nbq + 1], al, bh + 2);
                mma16816(d[2*nbq + 1], ah, bl + 2);
            }
        }

        if (t < 8) {
            __syncthreads();   // everyone done reading current B
            #pragma unroll
            for (int it = 0; it < 4; it++)
                *(uint4*)(smem + OF_B + (uint32_t)(tid + it*256)*16) = pre[it];
            __syncthreads();   // new B visible
        }
    }

    // ---- epilogue: D -> smem (stride 132), then coalesced store + fused stats ----
    __syncthreads();   // safe to overwrite window region
    float* epi = (float*)smem;
    #pragma unroll
    for (int n = 0; n < 8; n++)
        #pragma unroll
        for (int j = 0; j < 4; j++) {
            int co = n*8 + (lane & 3)*2 + (j & 1);
            int px = wid*16 + (lane >> 2) + ((j >> 1) << 3);
            epi[co*132 + px] = d[n][j];
        }
    __syncthreads();

    {
        const int h0 = tileH*4, w0 = tileW*32;
        #pragma unroll 1
        for (int k = 0; k < 8; k++) {
            const int co = wid*8 + k;
            const float bv = __ldg(bias + co);
            float* op = out + ((size_t)(b*64 + co))*HW + (size_t)h0*W + w0;
            float s = 0.f, q = 0.f;
            #pragma unroll
            for (int i = 0; i < 4; i++) {
                float v = epi[co*132 + i*32 + lane] + bv;
                op[(size_t)i*W + lane] = v;
                s += v; q += v*v;
            }
            #pragma unroll
            for (int off = 16; off; off >>= 1) {
                s += __shfl_down_sync(0xffffffffu, s, off);
                q += __shfl_down_sync(0xffffffffu, q, off);
            }
            if (lane == 0) {
                atomicAdd(&statacc[(b*64 + co)*2    ], s);
                atomicAdd(&statacc[(b*64 + co)*2 + 1], q);
            }
        }
    }
}

// ---------------- stats -> (mean, rstd) ----------------
__global__ void finalize_kernel(const float* __restrict__ acc, float* __restrict__ nrm) {
    int i = blockIdx.x * blockDim.x + threadIdx.x;
    if (i < BSZ*CH) {
        const float inv = 1.f / (float)HW;
        float m = acc[2*i] * inv;
        float v = acc[2*i + 1] * inv - m*m;
        nrm[2*i]     = m;
        nrm[2*i + 1] = rsqrtf(v + EPS);
    }
}

// ---------------- layer-0 scalar conv (cin=1, proven) ----------------
__global__ __launch_bounds__(256, 2)
void conv_kernel(const float* __restrict__ in,
                 const float* __restrict__ wgt,
                 const float* __restrict__ bias,
                 const float* __restrict__ innorm,
                 float* __restrict__ out,
                 float* __restrict__ statacc,
                 int cin)
{
    __shared__ float s_w[64*9*16];
    __shared__ float s_in[2][18*36];

    const int tid   = threadIdx.x;
    const int tileW = blockIdx.x & 7;
    const int tileH = blockIdx.x >> 3;
    const int co_base = blockIdx.y * 16;
    const int b = blockIdx.z;

    const int nw = cin * 9 * 16;
    for (int g = tid; g < nw; g += 256) {
        int co_l = g & 15;
        int ct   = g >> 4;
        int ci   = ct / 9;
        int t    = ct - ci*9;
        s_w[g] = wgt[((co_base + co_l)*cin + ci)*9 + t];
    }

    const int sp = tid & 63, cg = tid >> 6;
    const int ph = sp >> 3, pw = sp & 7;
    const int h0 = tileH*16 + ph*2;
    const int w0 = tileW*32 + pw*4;
    const int hbase = tileH*16 - 1, wbase = tileW*32 - 1;

    int srcO[3], dstO[3]; bool act[3];
    #pragma unroll
    for (int k = 0; k < 3; k++) {
        int g = tid + k*256;
        act[k] = (g < 612);
        int gg = act[k] ? g : 0;
        int r = gg / 34, c = gg - r * 34;
        int gh = hbase + r; gh = gh < 0 ? 0 : (gh > H-1 ? H-1 : gh);
        int gw = wbase + c; gw = gw < 0 ? 0 : (gw > W-1 ? W-1 : gw);
        srcO[k] = gh*W + gw;
        dstO[k] = r*36 + c;
    }

    const float* inb = in + (size_t)b * cin * HW;

    {
        float mean = 0.f, rstd = 1.f;
        if (innorm) { mean = innorm[(b*cin)*2]; rstd = innorm[(b*cin)*2+1]; }
        #pragma unroll
        for (int k = 0; k < 3; k++) if (act[k]) {
            float v = inb[srcO[k]];
            if (innorm) { v = (v - mean) * rstd; v = v >= 0.f ? v : SLOPE * v; }
            s_in[0][dstO[k]] = v;
        }
    }
    __syncthreads();

    u64 acc[2][2][4];
    #pragma unroll
    for (int p = 0; p < 2; p++)
        #pragma unroll
        for (int i = 0; i < 2; i++)
            #pragma unroll
            for (int j = 0; j < 4; j++) acc[p][i][j] = 0ull;

    for (int ci = 0; ci < cin; ci++) {
        const int buf = ci & 1;
        const int cn = (ci + 1 < cin) ? ci + 1 : cin - 1;

        float pre[3];
        float nmean = 0.f, nrstd = 1.f;
        {
            const float* pn = inb + (size_t)cn * HW;
            if (innorm) {
                nmean = innorm[(b*cin + cn)*2];
                nrstd = innorm[(b*cin + cn)*2 + 1];
            }
            #pragma unroll
            for (int k = 0; k < 3; k++) pre[k] = act[k] ? pn[srcO[k]] : 0.f;
        }

        u64 dup[4][6];
        #pragma unroll
        for (int r = 0; r < 4; r++) {
            const float* row = &s_in[buf][(ph*2 + r)*36 + pw*4];
            float4 v4 = *reinterpret_cast<const float4*>(row);
            float2 v2 = *reinterpret_cast<const float2*>(row + 4);
            PACK2(dup[r][0], v4.x, v4.x);
            PACK2(dup[r][1], v4.y, v4.y);
            PACK2(dup[r][2], v4.z, v4.z);
            PACK2(dup[r][3], v4.w, v4.w);
            PACK2(dup[r][4], v2.x, v2.x);
            PACK2(dup[r][5], v2.y, v2.y);
        }

        const float* wrow = &s_w[ci*9*16 + cg*4];
        #pragma unroll
        for (int p = 0; p < 2; p++) {
            u64 wv[9];
            #pragma unroll
            for (int t = 0; t < 9; t++)
                wv[t] = *reinterpret_cast<const u64*>(&wrow[t*16 + p*2]);
            #pragma unroll
            for (int kh = 0; kh < 3; kh++)
                #pragma unroll
                for (int kw = 0; kw < 3; kw++)
                    #pragma unroll
                    for (int i = 0; i < 2; i++)
                        #pragma unroll
                        for (int j = 0; j < 4; j++)
                            FMA2(acc[p][i][j], dup[i+kh][j+kw], wv[kh*3+kw], acc[p][i][j]);
        }

        #pragma unroll
        for (int k = 0; k < 3; k++) if (act[k]) {
            float v = pre[k];
            if (innorm) { v = (v - nmean) * nrstd; v = v >= 0.f ? v : SLOPE * v; }
            s_in[buf ^ 1][dstO[k]] = v;
        }
        __syncthreads();
    }

    #pragma unroll
    for (int p = 0; p < 2; p++) {
        const int co0 = co_base + cg*4 + 2*p;
        const float bv0 = bias[co0], bv1 = bias[co0 + 1];
        float* ob0 = out + (size_t)(b*CH + co0    ) * HW;
        float* ob1 = out + (size_t)(b*CH + co0 + 1) * HW;
        float s0 = 0.f, q0 = 0.f, s1 = 0.f, q1 = 0.f;
        #pragma unroll
        for (int i = 0; i < 2; i++) {
            float lo[4], hi[4];
            #pragma unroll
            for (int j = 0; j < 4; j++) {
                float l, h2;
                UNPK2(l, h2, acc[p][i][j]);
                lo[j] = l + bv0; hi[j] = h2 + bv1;
                s0 += lo[j]; q0 += lo[j]*lo[j];
                s1 += hi[j]; q1 += hi[j]*hi[j];
            }
            *reinterpret_cast<float4*>(&ob0[(h0+i)*W + w0]) = make_float4(lo[0],lo[1],lo[2],lo[3]);
            *reinterpret_cast<float4*>(&ob1[(h0+i)*W + w0]) = make_float4(hi[0],hi[1],hi[2],hi[3]);
        }
        #pragma unroll
        for (int off = 16; off; off >>= 1) {
            s0 += __shfl_down_sync(0xffffffffu, s0, off);
            q0 += __shfl_down_sync(0xffffffffu, q0, off);
            s1 += __shfl_down_sync(0xffffffffu, s1, off);
            q1 += __shfl_down_sync(0xffffffffu, q1, off);
        }
        if ((tid & 31) == 0) {
            atomicAdd(&statacc[(b*CH + co0)*2    ], s0);
            atomicAdd(&statacc[(b*CH + co0)*2 + 1], q0);
            atomicAdd(&statacc[(b*CH + co0+1)*2    ], s1);
            atomicAdd(&statacc[(b*CH + co0+1)*2 + 1], q1);
        }
    }
}

// ---------------- projection conv (64->1) + residual ----------------
__global__ __launch_bounds__(256)
void proj_kernel(const float* __restrict__ in, const float* __restrict__ innorm,
                 const float* __restrict__ wgt, const float* __restrict__ bias,
                 const float* __restrict__ xIn, float* __restrict__ out)
{
    __shared__ float s_w[64*9];
    __shared__ float s_in[18*18];
    const int tid = threadIdx.x;
    const int tileH = blockIdx.x >> 4, tileW = blockIdx.x & 15;
    const int b = blockIdx.z;

    for (int g = tid; g < 576; g += 256) s_w[g] = wgt[g];

    const int ph = tid >> 4, pw = tid & 15;
    const int h = tileH*16 + ph, w = tileW*16 + pw;
    const int hbase = tileH*16 - 1, wbase = tileW*16 - 1;
    const float* inb = in + (size_t)b * CH * HW;

    float acc = 0.f;
    for (int ci = 0; ci < CH; ci++) {
        __syncthreads();
        float mean = innorm[(b*CH + ci)*2];
        float rstd = innorm[(b*CH + ci)*2 + 1];
        const float* p = inb + ci * HW;
        for (int g = tid; g < 18*18; g += 256) {
            int r = g / 18, c = g - r*18;
            int gh = hbase + r; gh = gh < 0 ? 0 : (gh > H-1 ? H-1 : gh);
            int gw = wbase + c; gw = gw < 0 ? 0 : (gw > W-1 ? W-1 : gw);
            float v = p[gh*W + gw];
            v = (v - mean) * rstd;
            v = v >= 0.f ? v : SLOPE * v;
            s_in[g] = v;
        }
        __syncthreads();
        const float* wv = &s_w[ci*9];
        #pragma unroll
        for (int kh = 0; kh < 3; kh++)
            #pragma unroll
            for (int kw = 0; kw < 3; kw++)
                acc = fmaf(s_in[(ph + kh)*18 + pw + kw], wv[kh*3 + kw], acc);
    }
    int idx = b*HW + h*W + w;
    out[idx] = acc + bias[0] + xIn[idx];
}

// ---------------- shift-search loss ----------------
__global__ __launch_bounds__(256)
void loss_kernel(const float* __restrict__ hr, const float* __restrict__ tgt,
                 float* __restrict__ loss_sb)
{
    const int s = blockIdx.x, b = blockIdx.y;
    const int sy = s / 13, sx = s - sy*13;
    const float* hp = hr + (size_t)b * HW;
    const float* tp = tgt + (size_t)b * HW;
    const int tid = threadIdx.x;

    float sum = 0.f, sq = 0.f;
    if (tid < CROP) {
        for (int r = 0; r < CROP; r++) {
            float d = hp[(sy + r)*W + sx + tid] - tp[(6 + r)*W + 6 + tid];
            sum += d; sq += d*d;
        }
    }
    __shared__ float s1[256], s2[256];
    s1[tid] = sum; s2[tid] = sq;
    __syncthreads();
    for (int off = 128; off; off >>= 1) {
        if (tid < off) { s1[tid] += s1[tid + off]; s2[tid] += s2[tid + off]; }
        __syncthreads();
    }
    if (tid == 0) {
        const float invN = 1.f / (float)(CROP*CROP);
        float m = s1[0] * invN;
        loss_sb[s*BSZ + b] = s2[0] * invN - m*m;
    }
}

__global__ void loss_final_kernel(const float* __restrict__ loss_sb, float* __restrict__ out) {
    __shared__ float mn[BSZ];
    int t = threadIdx.x;
    if (t < BSZ) {
        float m = loss_sb[t];
        for (int s = 1; s < 169; s++) m = fminf(m, loss_sb[s*BSZ + t]);
        mn[t] = m;
    }
    __syncthreads();
    if (t == 0) {
        float a = 0.f;
        for (int b = 0; b < BSZ; b++) a += mn[b];
        out[0] = a * (1.f / BSZ);
    }
}

// ---------------- launch ----------------
extern "C" void kernel_launch(void* const* d_in, const int* in_sizes, int n_in,
                              void* d_out, int out_size)
{
    const float* xIn    = (const float*)d_in[0];
    const float* target = (const float*)d_in[1];
    const float* w0     = (const float*)d_in[2];
    const float* b0     = (const float*)d_in[3];
    const float* ws     = (const float*)d_in[4];
    const float* bs     = (const float*)d_in[5];
    const float* wp     = (const float*)d_in[6];
    const float* bp     = (const float*)d_in[7];
    float* out = (float*)d_out;

    static int attr_done = 0;
    if (!attr_done) {
        cudaFuncSetAttribute(mma_conv_kernel, cudaFuncAttributeMaxDynamicSharedMemorySize, SMEM_MMA);
        attr_done = 1;
    }

    float *actA, *actB, *stats, *nrm, *lsb;
    __nv_bfloat16* wprep;
    cudaGetSymbolAddress((void**)&actA,  g_actA);
    cudaGetSymbolAddress((void**)&actB,  g_actB);
    cudaGetSymbolAddress((void**)&stats, g_stats);
    cudaGetSymbolAddress((void**)&nrm,   g_norm);
    cudaGetSymbolAddress((void**)&lsb,   g_loss_sb);
    cudaGetSymbolAddress((void**)&wprep, g_wprep);

    wprep_kernel<<<dim3(9, 7), 256>>>(ws);
    zero_stats_kernel<<<1, 256>>>();

    // layer 0 (1 -> 64): scalar path, stats slot 0
    conv_kernel<<<dim3(128, 4, BSZ), 256>>>(xIn, w0, b0, nullptr, actA, stats, 1);
    finalize_kernel<<<2, 256>>>(stats, nrm);

    const float* cur = actA;
    float* nxt = actB;
    for (int i = 0; i < 7; i++) {
        mma_conv_kernel<<<dim3(8, 64, BSZ), 256, SMEM_MMA>>>(
            cur, wprep + (size_t)i*9*2*4096, bs + i*64,
            nrm + (size_t)i*BSZ*CH*2, nxt, stats + (size_t)(i+1)*BSZ*CH*2);
        finalize_kernel<<<2, 256>>>(stats + (size_t)(i+1)*BSZ*CH*2,
                                    nrm   + (size_t)(i+1)*BSZ*CH*2);
        float* tmp = (float*)cur; cur = nxt; nxt = tmp;
    }

    proj_kernel<<<dim3(256, 1, BSZ), 256>>>(cur, nrm + (size_t)7*BSZ*CH*2,
                                            wp, bp, xIn, out);
    loss_kernel<<<dim3(169, BSZ), 256>>>(out, target, lsb);
    loss_final_kernel<<<1, 32>>>(lsb, out + (out_size - 1));
}

// round 8
// speedup vs baseline: 4.3220x; 1.2068x over previous
#include <cuda_runtime.h>
#include <cuda_bf16.h>
#include <cuda_fp16.h>
#include <cstdint>

#define BSZ 8
#define CH  64
#define H   256
#define W   256
#define HW  (H*W)
#define EPS 1e-5f
#define SLOPE 0.01f
#define CROP 244

typedef unsigned long long u64;

#define FMA2(d,a,b,c) asm("fma.rn.f32x2 %0, %1, %2, %3;" : "=l"(d) : "l"(a), "l"(b), "l"(c))
#define PACK2(d,lo,hi) asm("mov.b64 %0, {%1, %2};" : "=l"(d) : "f"(lo), "f"(hi))
#define UNPK2(lo,hi,d) asm("mov.b64 {%0, %1}, %2;" : "=f"(lo), "=f"(hi) : "l"(d))

__device__ __forceinline__ uint32_t smem_u32(const void* p) {
    uint32_t a;
    asm("{ .reg .u64 t; cvta.to.shared.u64 t, %1; cvt.u32.u64 %0, t; }" : "=r"(a) : "l"(p));
    return a;
}
__device__ __forceinline__ void ldsm4(uint32_t* r, uint32_t addr) {
    asm volatile("ldmatrix.sync.aligned.m8n8.x4.shared.b16 {%0,%1,%2,%3}, [%4];"
                 : "=r"(r[0]), "=r"(r[1]), "=r"(r[2]), "=r"(r[3]) : "r"(addr));
}
__device__ __forceinline__ void mma16816h(float* d, const uint32_t* a, const uint32_t* b) {
    asm volatile("mma.sync.aligned.m16n8k16.row.col.f32.f16.f16.f32 "
                 "{%0,%1,%2,%3}, {%4,%5,%6,%7}, {%8,%9}, {%0,%1,%2,%3};"
                 : "+f"(d[0]), "+f"(d[1]), "+f"(d[2]), "+f"(d[3])
                 : "r"(a[0]), "r"(a[1]), "r"(a[2]), "r"(a[3]), "r"(b[0]), "r"(b[1]));
}

// ---------------- scratch ----------------
__device__ float g_actA[BSZ*CH*HW];
__device__ float g_actB[BSZ*CH*HW];
__device__ float g_stats[8*BSZ*CH*2];
__device__ float g_norm[8*BSZ*CH*2];
__device__ float g_loss_sb[169*BSZ];
__device__ __half g_wprep[7*9*4096];   // [layer][tap][64co x 64ci swizzled] fp16

__global__ void zero_stats_kernel() {
    for (int i = threadIdx.x; i < 8*BSZ*CH*2; i += blockDim.x) g_stats[i] = 0.f;
}

// ---------------- weight prep: fp16 + ldmatrix swizzle image ----------------
// layout: byte_off = co*128 + (((ci>>3) ^ (co&7))<<4) + (ci&7)*2
__global__ void wprep_kernel(const float* __restrict__ ws) {
    const int t = blockIdx.x;    // tap 0..8
    const int l = blockIdx.y;    // layer 0..6
    char* dst = (char*)(g_wprep + (size_t)(l*9 + t)*4096);
    for (int g = threadIdx.x; g < 4096; g += blockDim.x) {
        int co = g >> 6, ci = g & 63;
        float w = ws[(((size_t)l*64 + co)*64 + ci)*9 + t];
        uint32_t off = (uint32_t)co*128 + ((((uint32_t)ci >> 3) ^ (co & 7)) << 4) + (ci & 7)*2;
        *(__half*)(dst + off) = __float2half_rn(w);
    }
}

// ---------------- HMMA conv layer (fp16 2-pass split) ----------------
// smem: window xh [204*128B], window xl [204*128B], B dbl [2*8KB], nrm [512B]
#define OF_WHI 0
#define OF_WLO 26112
#define OF_B   52224
#define OF_NRM 68608
#define SMEM_MMA 69120

__global__ void __launch_bounds__(256, 2)
mma_conv_kernel(const float* __restrict__ in,
                const __half* __restrict__ wp,          // this layer: [9][4096]
                const float* __restrict__ bias,
                const float* __restrict__ nrm,          // [BSZ*64*2] (mean,rstd)
                float* __restrict__ out,
                float* __restrict__ statacc)            // [BSZ*64*2]
{
    extern __shared__ char smem[];
    const uint32_t sb = smem_u32(smem);
    const int tid = threadIdx.x;
    const int wid = tid >> 5, lane = tid & 31;
    const int tileW = blockIdx.x;   // 0..7
    const int tileH = blockIdx.y;   // 0..63
    const int b = blockIdx.z;

    // preload norm params for the 64 input channels
    if (tid < 64)
        *(float2*)(smem + OF_NRM + tid*8) = ((const float2*)nrm)[b*64 + tid];
    __syncthreads();   // nrm visible to ALL warps before window fill reads it

    // ---- window fill: 204 rows (6h x 34w) x 64 ci over ALL 256 threads ----
    // unit = (chunk, row): 8 chunks x 204 rows = 1632 units
    for (int g = tid; g < 1632; g += 256) {
        const int chunk = g / 204;
        const int r = g - chunk*204;
        const int rr = r / 34, cc = r - rr*34;
        int gh = tileH*4 - 1 + rr; gh = gh < 0 ? 0 : (gh > H-1 ? H-1 : gh);
        int gw = tileW*32 - 1 + cc; gw = gw < 0 ? 0 : (gw > W-1 ? W-1 : gw);
        const float* src = in + ((size_t)(b*64 + chunk*8))*HW + gh*W + gw;
        unsigned short hb[8], lb[8];
        #pragma unroll
        for (int q = 0; q < 8; q++) {
            const int ci = chunk*8 + q;
            float2 mr = *(const float2*)(smem + OF_NRM + ci*8);
            float x = __ldg(src + (size_t)q*HW);
            x = (x - mr.x) * mr.y;
            x = x >= 0.f ? x : SLOPE * x;
            __half h = __float2half_rn(x);
            __half l = __float2half_rn(x - __half2float(h));
            hb[q] = *(unsigned short*)&h;
            lb[q] = *(unsigned short*)&l;
        }
        const uint32_t off = (uint32_t)r*128 + (uint32_t)((chunk ^ (r & 7)) << 4);
        *(uint4*)(smem + OF_WHI + off) = *(uint4*)hb;
        *(uint4*)(smem + OF_WLO + off) = *(uint4*)lb;
    }

    // ---- stage B for tap 0 into buffer 0 ----
    const uint4* wp4 = (const uint4*)wp;   // [9][512] uint4
    {
        *(uint4*)(smem + OF_B + (uint32_t)tid*16)         = __ldg(wp4 + tid);
        *(uint4*)(smem + OF_B + (uint32_t)(tid + 256)*16) = __ldg(wp4 + tid + 256);
    }
    __syncthreads();

    // warp geometry
    const int hl  = wid >> 1;            // 0..3
    const int wlb = (wid & 1) * 16;      // 0 or 16
    const int gA  = lane >> 3;           // ldmatrix group
    const int rl  = (lane & 7) + (gA & 1)*8;
    const int aK  = gA >> 1;
    const int bRow = (lane & 7) + ((lane >> 4) & 1)*8;
    const int bK   = (lane >> 3) & 1;
    const int bsw  = lane & 7;

    float d[8][4];
    #pragma unroll
    for (int n = 0; n < 8; n++)
        #pragma unroll
        for (int j = 0; j < 4; j++) d[n][j] = 0.f;

    #pragma unroll 1
    for (int t = 0; t < 9; t++) {
        // prefetch next tap's B image (into regs)
        uint4 pre[2];
        if (t < 8) {
            const uint4* np = wp4 + (size_t)(t + 1)*512;
            pre[0] = __ldg(np + tid);
            pre[1] = __ldg(np + tid + 256);
        }

        const int kh = t / 3, kw = t - kh*3;
        const int wrA = (hl + kh)*34 + wlb + kw + rl;
        const uint32_t aHi = sb + OF_WHI + (uint32_t)wrA*128;
        const uint32_t aLo = sb + OF_WLO + (uint32_t)wrA*128;
        const int asw = wrA & 7;
        const uint32_t bB = sb + OF_B + (uint32_t)(t & 1)*8192;

        #pragma unroll
        for (int ks = 0; ks < 4; ks++) {
            uint32_t ah[4], al[4];
            const uint32_t ca = (uint32_t)(((2*ks + aK) ^ asw) << 4);
            ldsm4(ah, aHi + ca);
            ldsm4(al, aLo + ca);
            const uint32_t cboff = (uint32_t)(((2*ks + bK) ^ bsw) << 4);
            #pragma unroll
            for (int nbq = 0; nbq < 4; nbq++) {
                uint32_t bh[4];
                ldsm4(bh, bB + (uint32_t)(nbq*16 + bRow)*128 + cboff);
                mma16816h(d[2*nbq    ], ah, bh    );
                mma16816h(d[2*nbq    ], al, bh    );
                mma16816h(d[2*nbq + 1], ah, bh + 2);
                mma16816h(d[2*nbq + 1], al, bh + 2);
            }
        }

        if (t < 8) {
            // store prefetched B into the OTHER buffer (its last readers finished
            // at the barrier ending tap t-1), then one barrier to publish
            char* dst = smem + OF_B + (uint32_t)((t + 1) & 1)*8192;
            *(uint4*)(dst + (uint32_t)tid*16)         = pre[0];
            *(uint4*)(dst + (uint32_t)(tid + 256)*16) = pre[1];
            __syncthreads();
        }
    }

    // ---- epilogue: D -> smem (stride 132), then coalesced store + fused stats ----
    __syncthreads();   // safe to overwrite window region
    float* epi = (float*)smem;
    #pragma unroll
    for (int n = 0; n < 8; n++)
        #pragma unroll
        for (int j = 0; j < 4; j++) {
            int co = n*8 + (lane & 3)*2 + (j & 1);
            int px = wid*16 + (lane >> 2) + ((j >> 1) << 3);
            epi[co*132 + px] = d[n][j];
        }
    __syncthreads();

    {
        const int h0 = tileH*4, w0 = tileW*32;
        #pragma unroll 1
        for (int k = 0; k < 8; k++) {
            const int co = wid*8 + k;
            const float bv = __ldg(bias + co);
            float* op = out + ((size_t)(b*64 + co))*HW + (size_t)h0*W + w0;
            float s = 0.f, q = 0.f;
            #pragma unroll
            for (int i = 0; i < 4; i++) {
                float v = epi[co*132 + i*32 + lane] + bv;
                op[(size_t)i*W + lane] = v;
                s += v; q += v*v;
            }
            #pragma unroll
            for (int off = 16; off; off >>= 1) {
                s += __shfl_down_sync(0xffffffffu, s, off);
                q += __shfl_down_sync(0xffffffffu, q, off);
            }
            if (lane == 0) {
                atomicAdd(&statacc[(b*64 + co)*2    ], s);
                atomicAdd(&statacc[(b*64 + co)*2 + 1], q);
            }
        }
    }
}

// ---------------- stats -> (mean, rstd) ----------------
__global__ void finalize_kernel(const float* __restrict__ acc, float* __restrict__ nrm) {
    int i = blockIdx.x * blockDim.x + threadIdx.x;
    if (i < BSZ*CH) {
        const float inv = 1.f / (float)HW;
        float m = acc[2*i] * inv;
        float v = acc[2*i + 1] * inv - m*m;
        nrm[2*i]     = m;
        nrm[2*i + 1] = rsqrtf(v + EPS);
    }
}

// ---------------- layer-0 scalar conv (cin=1, proven) ----------------
__global__ __launch_bounds__(256, 2)
void conv_kernel(const float* __restrict__ in,
                 const float* __restrict__ wgt,
                 const float* __restrict__ bias,
                 const float* __restrict__ innorm,
                 float* __restrict__ out,
                 float* __restrict__ statacc,
                 int cin)
{
    __shared__ float s_w[64*9*16];
    __shared__ float s_in[2][18*36];

    const int tid   = threadIdx.x;
    const int tileW = blockIdx.x & 7;
    const int tileH = blockIdx.x >> 3;
    const int co_base = blockIdx.y * 16;
    const int b = blockIdx.z;

    const int nw = cin * 9 * 16;
    for (int g = tid; g < nw; g += 256) {
        int co_l = g & 15;
        int ct   = g >> 4;
        int ci   = ct / 9;
        int t    = ct - ci*9;
        s_w[g] = wgt[((co_base + co_l)*cin + ci)*9 + t];
    }

    const int sp = tid & 63, cg = tid >> 6;
    const int ph = sp >> 3, pw = sp & 7;
    const int h0 = tileH*16 + ph*2;
    const int w0 = tileW*32 + pw*4;
    const int hbase = tileH*16 - 1, wbase = tileW*32 - 1;

    int srcO[3], dstO[3]; bool act[3];
    #pragma unroll
    for (int k = 0; k < 3; k++) {
        int g = tid + k*256;
        act[k] = (g < 612);
        int gg = act[k] ? g : 0;
        int r = gg / 34, c = gg - r * 34;
        int gh = hbase + r; gh = gh < 0 ? 0 : (gh > H-1 ? H-1 : gh);
        int gw = wbase + c; gw = gw < 0 ? 0 : (gw > W-1 ? W-1 : gw);
        srcO[k] = gh*W + gw;
        dstO[k] = r*36 + c;
    }

    const float* inb = in + (size_t)b * cin * HW;

    {
        float mean = 0.f, rstd = 1.f;
        if (innorm) { mean = innorm[(b*cin)*2]; rstd = innorm[(b*cin)*2+1]; }
        #pragma unroll
        for (int k = 0; k < 3; k++) if (act[k]) {
            float v = inb[srcO[k]];
            if (innorm) { v = (v - mean) * rstd; v = v >= 0.f ? v : SLOPE * v; }
            s_in[0][dstO[k]] = v;
        }
    }
    __syncthreads();

    u64 acc[2][2][4];
    #pragma unroll
    for (int p = 0; p < 2; p++)
        #pragma unroll
        for (int i = 0; i < 2; i++)
            #pragma unroll
            for (int j = 0; j < 4; j++) acc[p][i][j] = 0ull;

    for (int ci = 0; ci < cin; ci++) {
        const int buf = ci & 1;
        const int cn = (ci + 1 < cin) ? ci + 1 : cin - 1;

        float pre[3];
        float nmean = 0.f, nrstd = 1.f;
        {
            const float* pn = inb + (size_t)cn * HW;
            if (innorm) {
                nmean = innorm[(b*cin + cn)*2];
                nrstd = innorm[(b*cin + cn)*2 + 1];
            }
            #pragma unroll
            for (int k = 0; k < 3; k++) pre[k] = act[k] ? pn[srcO[k]] : 0.f;
        }

        u64 dup[4][6];
        #pragma unroll
        for (int r = 0; r < 4; r++) {
            const float* row = &s_in[buf][(ph*2 + r)*36 + pw*4];
            float4 v4 = *reinterpret_cast<const float4*>(row);
            float2 v2 = *reinterpret_cast<const float2*>(row + 4);
            PACK2(dup[r][0], v4.x, v4.x);
            PACK2(dup[r][1], v4.y, v4.y);
            PACK2(dup[r][2], v4.z, v4.z);
            PACK2(dup[r][3], v4.w, v4.w);
            PACK2(dup[r][4], v2.x, v2.x);
            PACK2(dup[r][5], v2.y, v2.y);
        }

        const float* wrow = &s_w[ci*9*16 + cg*4];
        #pragma unroll
        for (int p = 0; p < 2; p++) {
            u64 wv[9];
            #pragma unroll
            for (int t = 0; t < 9; t++)
                wv[t] = *reinterpret_cast<const u64*>(&wrow[t*16 + p*2]);
            #pragma unroll
            for (int kh = 0; kh < 3; kh++)
                #pragma unroll
                for (int kw = 0; kw < 3; kw++)
                    #pragma unroll
                    for (int i = 0; i < 2; i++)
                        #pragma unroll
                        for (int j = 0; j < 4; j++)
                            FMA2(acc[p][i][j], dup[i+kh][j+kw], wv[kh*3+kw], acc[p][i][j]);
        }

        #pragma unroll
        for (int k = 0; k < 3; k++) if (act[k]) {
            float v = pre[k];
            if (innorm) { v = (v - nmean) * nrstd; v = v >= 0.f ? v : SLOPE * v; }
            s_in[buf ^ 1][dstO[k]] = v;
        }
        __syncthreads();
    }

    #pragma unroll
    for (int p = 0; p < 2; p++) {
        const int co0 = co_base + cg*4 + 2*p;
        const float bv0 = bias[co0], bv1 = bias[co0 + 1];
        float* ob0 = out + (size_t)(b*CH + co0    ) * HW;
        float* ob1 = out + (size_t)(b*CH + co0 + 1) * HW;
        float s0 = 0.f, q0 = 0.f, s1 = 0.f, q1 = 0.f;
        #pragma unroll
        for (int i = 0; i < 2; i++) {
            float lo[4], hi[4];
            #pragma unroll
            for (int j = 0; j < 4; j++) {
                float l, h2;
                UNPK2(l, h2, acc[p][i][j]);
                lo[j] = l + bv0; hi[j] = h2 + bv1;
                s0 += lo[j]; q0 += lo[j]*lo[j];
                s1 += hi[j]; q1 += hi[j]*hi[j];
            }
            *reinterpret_cast<float4*>(&ob0[(h0+i)*W + w0]) = make_float4(lo[0],lo[1],lo[2],lo[3]);
            *reinterpret_cast<float4*>(&ob1[(h0+i)*W + w0]) = make_float4(hi[0],hi[1],hi[2],hi[3]);
        }
        #pragma unroll
        for (int off = 16; off; off >>= 1) {
            s0 += __shfl_down_sync(0xffffffffu, s0, off);
            q0 += __shfl_down_sync(0xffffffffu, q0, off);
            s1 += __shfl_down_sync(0xffffffffu, s1, off);
            q1 += __shfl_down_sync(0xffffffffu, q1, off);
        }
        if ((tid & 31) == 0) {
            atomicAdd(&statacc[(b*CH + co0)*2    ], s0);
            atomicAdd(&statacc[(b*CH + co0)*2 + 1], q0);
            atomicAdd(&statacc[(b*CH + co0+1)*2    ], s1);
            atomicAdd(&statacc[(b*CH + co0+1)*2 + 1], q1);
        }
    }
}

// ---------------- projection conv (64->1) + residual ----------------
__global__ __launch_bounds__(256)
void proj_kernel(const float* __restrict__ in, const float* __restrict__ innorm,
                 const float* __restrict__ wgt, const float* __restrict__ bias,
                 const float* __restrict__ xIn, float* __restrict__ out)
{
    __shared__ float s_w[64*9];
    __shared__ float s_in[18*18];
    const int tid = threadIdx.x;
    const int tileH = blockIdx.x >> 4, tileW = blockIdx.x & 15;
    const int b = blockIdx.z;

    for (int g = tid; g < 576; g += 256) s_w[g] = wgt[g];

    const int ph = tid >> 4, pw = tid & 15;
    const int h = tileH*16 + ph, w = tileW*16 + pw;
    const int hbase = tileH*16 - 1, wbase = tileW*16 - 1;
    const float* inb = in + (size_t)b * CH * HW;

    float acc = 0.f;
    for (int ci = 0; ci < CH; ci++) {
        __syncthreads();
        float mean = innorm[(b*CH + ci)*2];
        float rstd = innorm[(b*CH + ci)*2 + 1];
        const float* p = inb + ci * HW;
        for (int g = tid; g < 18*18; g += 256) {
            int r = g / 18, c = g - r*18;
            int gh = hbase + r; gh = gh < 0 ? 0 : (gh > H-1 ? H-1 : gh);
            int gw = wbase + c; gw = gw < 0 ? 0 : (gw > W-1 ? W-1 : gw);
            float v = p[gh*W + gw];
            v = (v - mean) * rstd;
            v = v >= 0.f ? v : SLOPE * v;
            s_in[g] = v;
        }
        __syncthreads();
        const float* wv = &s_w[ci*9];
        #pragma unroll
        for (int kh = 0; kh < 3; kh++)
            #pragma unroll
            for (int kw = 0; kw < 3; kw++)
                acc = fmaf(s_in[(ph + kh)*18 + pw + kw], wv[kh*3 + kw], acc);
    }
    int idx = b*HW + h*W + w;
    out[idx] = acc + bias[0] + xIn[idx];
}

// ---------------- shift-search loss ----------------
__global__ __launch_bounds__(256)
void loss_kernel(const float* __restrict__ hr, const float* __restrict__ tgt,
                 float* __restrict__ loss_sb)
{
    const int s = blockIdx.x, b = blockIdx.y;
    const int sy = s / 13, sx = s - sy*13;
    const float* hp = hr + (size_t)b * HW;
    const float* tp = tgt + (size_t)b * HW;
    const int tid = threadIdx.x;

    float sum = 0.f, sq = 0.f;
    if (tid < CROP) {
        for (int r = 0; r < CROP; r++) {
            float d = hp[(sy + r)*W + sx + tid] - tp[(6 + r)*W + 6 + tid];
            sum += d; sq += d*d;
        }
    }
    __shared__ float s1[256], s2[256];
    s1[tid] = sum; s2[tid] = sq;
    __syncthreads();
    for (int off = 128; off; off >>= 1) {
        if (tid < off) { s1[tid] += s1[tid + off]; s2[tid] += s2[tid + off]; }
        __syncthreads();
    }
    if (tid == 0) {
        const float invN = 1.f / (float)(CROP*CROP);
        float m = s1[0] * invN;
        loss_sb[s*BSZ + b] = s2[0] * invN - m*m;
    }
}

__global__ void loss_final_kernel(const float* __restrict__ loss_sb, float* __restrict__ out) {
    __shared__ float mn[BSZ];
    int t = threadIdx.x;
    if (t < BSZ) {
        float m = loss_sb[t];
        for (int s = 1; s < 169; s++) m = fminf(m, loss_sb[s*BSZ + t]);
        mn[t] = m;
    }
    __syncthreads();
    if (t == 0) {
        float a = 0.f;
        for (int b = 0; b < BSZ; b++) a += mn[b];
        out[0] = a * (1.f / BSZ);
    }
}

// ---------------- launch ----------------
extern "C" void kernel_launch(void* const* d_in, const int* in_sizes, int n_in,
                              void* d_out, int out_size)
{
    const float* xIn    = (const float*)d_in[0];
    const float* target = (const float*)d_in[1];
    const float* w0     = (const float*)d_in[2];
    const float* b0     = (const float*)d_in[3];
    const float* ws     = (const float*)d_in[4];
    const float* bs     = (const float*)d_in[5];
    const float* wp     = (const float*)d_in[6];
    const float* bp     = (const float*)d_in[7];
    float* out = (float*)d_out;

    static int attr_done = 0;
    if (!attr_done) {
        cudaFuncSetAttribute(mma_conv_kernel, cudaFuncAttributeMaxDynamicSharedMemorySize, SMEM_MMA);
        attr_done = 1;
    }

    float *actA, *actB, *stats, *nrm, *lsb;
    __half* wprep;
    cudaGetSymbolAddress((void**)&actA,  g_actA);
    cudaGetSymbolAddress((void**)&actB,  g_actB);
    cudaGetSymbolAddress((void**)&stats, g_stats);
    cudaGetSymbolAddress((void**)&nrm,   g_norm);
    cudaGetSymbolAddress((void**)&lsb,   g_loss_sb);
    cudaGetSymbolAddress((void**)&wprep, g_wprep);

    wprep_kernel<<<dim3(9, 7), 256>>>(ws);
    zero_stats_kernel<<<1, 256>>>();

    // layer 0 (1 -> 64): scalar path, stats slot 0
    conv_kernel<<<dim3(128, 4, BSZ), 256>>>(xIn, w0, b0, nullptr, actA, stats, 1);
    finalize_kernel<<<2, 256>>>(stats, nrm);

    const float* cur = actA;
    float* nxt = actB;
    for (int i = 0; i < 7; i++) {
        mma_conv_kernel<<<dim3(8, 64, BSZ), 256, SMEM_MMA>>>(
            cur, wprep + (size_t)i*9*4096, bs + i*64,
            nrm + (size_t)i*BSZ*CH*2, nxt, stats + (size_t)(i+1)*BSZ*CH*2);
        finalize_kernel<<<2, 256>>>(stats + (size_t)(i+1)*BSZ*CH*2,
                                    nrm   + (size_t)(i+1)*BSZ*CH*2);
        float* tmp = (float*)cur; cur = nxt; nxt = tmp;
    }

    proj_kernel<<<dim3(256, 1, BSZ), 256>>>(cur, nrm + (size_t)7*BSZ*CH*2,
                                            wp, bp, xIn, out);
    loss_kernel<<<dim3(169, BSZ), 256>>>(out, target, lsb);
    loss_final_kernel<<<1, 32>>>(lsb, out + (out_size - 1));
}